// round 1
// baseline (speedup 1.0000x reference)
#include <cuda_runtime.h>
#include <math.h>

// Problem constants
#define BB 4
#define SS 4096
#define NN 4096
#define CC 32

#define NSPLIT 4
#define TS 64          // s-values per block
#define TN 32          // n-values per chunk
#define NPB (NN/NSPLIT)   // 1024 n per block
#define NCHUNK (NPB/TN)   // 32 chunks

// Scratch: [split][b][s][c] float2 (re, im) = 4*4*4096*32*8B = 16.8MB
__device__ float2 g_scratch[NSPLIT * BB * SS * CC];

// ---- packed f32x2 helpers (PTX-only instructions on sm_103a) ----
__device__ __forceinline__ unsigned long long pk2(float lo, float hi) {
    unsigned long long r;
    asm("mov.b64 %0, {%1, %2};" : "=l"(r) : "f"(lo), "f"(hi));
    return r;
}
__device__ __forceinline__ float2 upk2(unsigned long long v) {
    float lo, hi;
    asm("mov.b64 {%0, %1}, %2;" : "=f"(lo), "=f"(hi) : "l"(v));
    return make_float2(lo, hi);
}
__device__ __forceinline__ void fma2(unsigned long long& acc,
                                     unsigned long long a,
                                     unsigned long long b) {
    asm("fma.rn.f32x2 %0, %1, %2, %0;" : "+l"(acc) : "l"(a), "l"(b));
}

// Reduction constants: phase = k*pi + r, |r| <= pi/2
#define INVPI 0.3183098861837907f
#define PI_A  3.14159274101257324f      /* fl(pi)        */
#define PI_B  (-8.742277657347586e-8f)  /* pi - fl(pi)   */

// Taylor coefficients (|x|<=pi/2: sin err ~6e-8, cos err ~7e-9)
#define S3  (-1.6666666666e-1f)
#define S5  ( 8.3333333333e-3f)
#define S7  (-1.9841269841e-4f)
#define S9  ( 2.7557319224e-6f)
#define S11 (-2.5052108385e-8f)
#define C2  (-5.0000000000e-1f)
#define C4  ( 4.1666666667e-2f)
#define C6  (-1.3888888889e-3f)
#define C8  ( 2.4801587302e-5f)
#define C10 (-2.7557319224e-7f)
#define C12 ( 2.0876756988e-9f)

__global__ __launch_bounds__(64)
void fudft_partial(const float* __restrict__ x,
                   const float* __restrict__ t,
                   const float* __restrict__ freqs) {
    // cs_tile: 64 rows (s) x 64 floats; entry (s,n) is float2 (cos,sin) at
    // column (2n) ^ (2*((s>>2)&7) + 16*(s&1))  -- conflict-free for gen & mac
    __shared__ float cs_tile[TS * 64];
    __shared__ float xs[TN * CC];
    __shared__ float cols_sm[TN];

    const int bx    = blockIdx.x;          // 0..1023
    const int g     = bx & (NSPLIT - 1);   // n-split
    const int stile = (bx >> 2) & 63;      // s tile
    const int b     = bx >> 8;             // batch
    const int tid   = threadIdx.x;         // 0..63

    // ---- gen-stage per-thread setup: this thread generates row s_loc ----
    const int   s_loc  = tid;
    const int   s_glob = stile * TS + s_loc;
    // match reference rounding: rows = (freqs*4095) * fl(-2*pi/4096)
    const float r_s = (freqs[s_glob] * 4095.0f) * (-1.5339807878856412e-3f);
    const int   swz = 2 * ((s_loc >> 2) & 7) + 16 * (s_loc & 1);
    float* genrow = cs_tile + s_loc * 64;

    // ---- mac-stage per-thread setup: 4 s x 8 c register tile ----
    const int sg = tid >> 2;               // 0..15 -> s = sg*4 + ii
    const int cg = tid & 3;                // 0..3  -> c = cg*8 + j
    const int k2 = 2 * (sg & 7);
    const float* r0 = cs_tile + (sg * 4 + 0) * 64;
    const float* r1 = cs_tile + (sg * 4 + 1) * 64;
    const float* r2p = cs_tile + (sg * 4 + 2) * 64;
    const float* r3 = cs_tile + (sg * 4 + 3) * 64;
    const float* xp = xs + cg * 8;

    unsigned long long accre[4][4], accim[4][4];
#pragma unroll
    for (int i = 0; i < 4; ++i)
#pragma unroll
        for (int j = 0; j < 4; ++j) { accre[i][j] = 0ull; accim[i][j] = 0ull; }

    const float* xrow = x + (size_t)b * NN * CC;
    const float* trow = t + (size_t)b * NN;

    for (int chunk = 0; chunk < NCHUNK; ++chunk) {
        const int n0 = g * NPB + chunk * TN;

        __syncthreads();   // previous MAC done: safe to overwrite tiles
        if (tid < TN) cols_sm[tid] = trow[n0 + tid] * 4095.0f;
        {
            const float4* xg  = (const float4*)(xrow + (size_t)n0 * CC);
            float4*       xs4 = (float4*)xs;
#pragma unroll
            for (int r = 0; r < 4; ++r) xs4[tid + 64 * r] = xg[tid + 64 * r];
        }
        __syncthreads();   // cols_sm / xs visible

        // ---- GEN: 32 (cos,sin) entries for row s_loc ----
#pragma unroll 4
        for (int n = 0; n < TN; ++n) {
            float ph = r_s * cols_sm[n];               // matches reference fp32 mul
            float kf = rintf(ph * INVPI);
            float rr = fmaf(kf, -PI_A, ph);
            rr       = fmaf(kf, -PI_B, rr);
            int   ki = (int)kf;
            float sgn = __uint_as_float(0x3f800000u ^ (((unsigned)ki & 1u) << 31));
            float q  = rr * rr;
            float sp = fmaf(q, S11, S9);
            sp = fmaf(q, sp, S7); sp = fmaf(q, sp, S5);
            sp = fmaf(q, sp, S3); sp = fmaf(q, sp, 1.0f);
            float sv = (rr * sgn) * sp;
            float cp = fmaf(q, C12, C10);
            cp = fmaf(q, cp, C8); cp = fmaf(q, cp, C6);
            cp = fmaf(q, cp, C4); cp = fmaf(q, cp, C2);
            cp = fmaf(q, cp, 1.0f);
            float cv = cp * sgn;
            int col = (2 * n) ^ swz;
            *(float2*)(genrow + col) = make_float2(cv, sv);
        }
        __syncthreads();   // cs_tile ready

        // ---- MAC: 4s x 8c, packed f32x2 FMAs ----
#pragma unroll 4
        for (int n = 0; n < TN; ++n) {
            const int c0 = (2 * n) ^ k2;
            const int c1 = c0 ^ 16;
            float2 cs0 = *(const float2*)(r0  + c0);
            float2 cs1 = *(const float2*)(r1  + c1);
            float2 cs2 = *(const float2*)(r2p + c0);
            float2 cs3 = *(const float2*)(r3  + c1);
            float4 xa = *(const float4*)(xp + n * CC);
            float4 xb = *(const float4*)(xp + n * CC + 4);

            unsigned long long xq[4];
            xq[0] = pk2(xa.x, xa.y); xq[1] = pk2(xa.z, xa.w);
            xq[2] = pk2(xb.x, xb.y); xq[3] = pk2(xb.z, xb.w);

            unsigned long long cc0 = pk2(cs0.x, cs0.x), ss0 = pk2(cs0.y, cs0.y);
            unsigned long long cc1 = pk2(cs1.x, cs1.x), ss1 = pk2(cs1.y, cs1.y);
            unsigned long long cc2 = pk2(cs2.x, cs2.x), ss2 = pk2(cs2.y, cs2.y);
            unsigned long long cc3 = pk2(cs3.x, cs3.x), ss3 = pk2(cs3.y, cs3.y);

#pragma unroll
            for (int j = 0; j < 4; ++j) {
                fma2(accre[0][j], cc0, xq[j]); fma2(accim[0][j], ss0, xq[j]);
                fma2(accre[1][j], cc1, xq[j]); fma2(accim[1][j], ss1, xq[j]);
                fma2(accre[2][j], cc2, xq[j]); fma2(accim[2][j], ss2, xq[j]);
                fma2(accre[3][j], cc3, xq[j]); fma2(accim[3][j], ss3, xq[j]);
            }
        }
    }

    // ---- write partials: scratch[(g*BB+b)][s][c] ----
    float2* scr = g_scratch + ((size_t)(g * BB + b) * SS + (size_t)stile * TS) * CC;
#pragma unroll
    for (int ii = 0; ii < 4; ++ii) {
        const int srow = sg * 4 + ii;
#pragma unroll
        for (int j = 0; j < 4; ++j) {
            float2 re2 = upk2(accre[ii][j]);
            float2 im2 = upk2(accim[ii][j]);
            const int c = cg * 8 + j * 2;
            scr[srow * CC + c]     = make_float2(re2.x, im2.x);
            scr[srow * CC + c + 1] = make_float2(re2.y, im2.y);
        }
    }
}

__global__ __launch_bounds__(256)
void fudft_reduce(float* __restrict__ out) {
    const int idx = blockIdx.x * blockDim.x + threadIdx.x;   // 0..524287
    float re = 0.0f, im = 0.0f;
#pragma unroll
    for (int g = 0; g < NSPLIT; ++g) {
        float2 p = g_scratch[(size_t)g * (BB * SS * CC) + idx];
        re += p.x; im += p.y;
    }
    float mag = sqrtf(fmaf(re, re, im * im)) * 0.015625f;    // * 1/sqrt(4096)
    const int s = (idx >> 5) & (SS - 1);
    if (s == 0 || s == SS - 1) mag = 0.0f;
    out[idx] = mag;
}

extern "C" void kernel_launch(void* const* d_in, const int* in_sizes, int n_in,
                              void* d_out, int out_size) {
    const float* x     = (const float*)d_in[0];   // [4,4096,32]
    const float* t     = (const float*)d_in[1];   // [4,4096]
    const float* freqs = (const float*)d_in[2];   // [4096]
    float* out = (float*)d_out;                   // [4,4096,32]

    fudft_partial<<<BB * (SS / TS) * NSPLIT, 64>>>(x, t, freqs);
    fudft_reduce<<<(BB * SS * CC) / 256, 256>>>(out);
}

// round 2
// speedup vs baseline: 1.2256x; 1.2256x over previous
#include <cuda_runtime.h>
#include <math.h>

// Problem constants
#define BB 4
#define SS 4096
#define NN 4096
#define CC 32

#define NSPLIT 4
#define TS 64             // s-values per block
#define TN 32             // n-values per chunk
#define NPB (NN/NSPLIT)   // 1024 n per block
#define NCHUNK (NPB/TN)   // 32 chunks

typedef unsigned long long ull;

// Scratch: [split][b][s][c] float2 (re, im) = 4*4*4096*32*8B = 16.8MB
__device__ float2 g_scratch[NSPLIT * BB * SS * CC];

// ---- packed f32x2 helpers (PTX-only instructions on sm_103a) ----
__device__ __forceinline__ ull pk2(float lo, float hi) {
    ull r;
    asm("mov.b64 %0, {%1, %2};" : "=l"(r) : "f"(lo), "f"(hi));
    return r;
}
__device__ __forceinline__ float2 upk2(ull v) {
    float lo, hi;
    asm("mov.b64 {%0, %1}, %2;" : "=f"(lo), "=f"(hi) : "l"(v));
    return make_float2(lo, hi);
}
__device__ __forceinline__ void fma2(ull& acc, ull a, ull b) {
    asm("fma.rn.f32x2 %0, %1, %2, %0;" : "+l"(acc) : "l"(a), "l"(b));
}
__device__ __forceinline__ ull fma2n(ull a, ull b, ull c) {
    ull r;
    asm("fma.rn.f32x2 %0, %1, %2, %3;" : "=l"(r) : "l"(a), "l"(b), "l"(c));
    return r;
}
__device__ __forceinline__ ull mul2(ull a, ull b) {
    ull r;
    asm("mul.rn.f32x2 %0, %1, %2;" : "=l"(r) : "l"(a), "l"(b));
    return r;
}
__device__ __forceinline__ ull add2(ull a, ull b) {
    ull r;
    asm("add.rn.f32x2 %0, %1, %2;" : "=l"(r) : "l"(a), "l"(b));
    return r;
}

// Range reduction constants: phase = k*2pi + r, |r| <= pi (+eps)
#define INV2PI   0.15915493667125701904f   /* fl(1/(2pi)) */
#define TWOPI_A  6.28318548202514648438f   /* fl(2pi) */
#define TWOPI_B  (-1.74845552749343265e-7f)/* 2pi - fl(2pi) */
#define MAGIC    12582912.0f               /* 1.5 * 2^23 */

__global__ __launch_bounds__(64)
void fudft_partial(const float* __restrict__ x,
                   const float* __restrict__ t,
                   const float* __restrict__ freqs) {
    // cs_tile: 64 rows (s) x 64 floats; entry (s,n) is float2 (cos,sin) at
    // column (2n) ^ (2*((s>>2)&7) + 16*(s&1))  -- conflict-free for gen & mac
    __shared__ __align__(16) float cs_tile[TS * 64];
    __shared__ __align__(16) float xs[TN * CC];
    __shared__ __align__(16) float cols_sm[TN];

    const int bx    = blockIdx.x;          // 0..1023
    const int g     = bx & (NSPLIT - 1);   // n-split
    const int stile = (bx >> 2) & 63;      // s tile
    const int b     = bx >> 8;             // batch
    const int tid   = threadIdx.x;         // 0..63

    // ---- gen-stage per-thread setup: this thread generates row s_loc ----
    const int   s_loc  = tid;
    const int   s_glob = stile * TS + s_loc;
    // match reference rounding: rows = (freqs*4095) * fl(-2*pi/4096)
    const float r_s = (freqs[s_glob] * 4095.0f) * (-1.5339807878856412e-3f);
    const int   swz = 2 * ((s_loc >> 2) & 7) + 16 * (s_loc & 1);
    float* genrow = cs_tile + s_loc * 64;

    // packed constants for the gen reduction (hoisted)
    const ull r_s2    = pk2(r_s, r_s);
    const ull inv2pi2 = pk2(INV2PI, INV2PI);
    const ull magic2  = pk2(MAGIC, MAGIC);
    const ull nmagic2 = pk2(-MAGIC, -MAGIC);
    const ull nA2     = pk2(-TWOPI_A, -TWOPI_A);
    const ull nB2     = pk2(-TWOPI_B, -TWOPI_B);

    // ---- mac-stage per-thread setup: 4 s x 8 c register tile ----
    const int sg = tid >> 2;               // 0..15 -> s = sg*4 + ii
    const int cg = tid & 3;                // 0..3  -> c = cg*8 + j
    const int k2 = 2 * (sg & 7);
    const float* r0 = cs_tile + (sg * 4 + 0) * 64;
    const float* r1 = cs_tile + (sg * 4 + 1) * 64;
    const float* r2p = cs_tile + (sg * 4 + 2) * 64;
    const float* r3 = cs_tile + (sg * 4 + 3) * 64;
    const float* xp = xs + cg * 8;

    ull accre[4][4], accim[4][4];
#pragma unroll
    for (int i = 0; i < 4; ++i)
#pragma unroll
        for (int j = 0; j < 4; ++j) { accre[i][j] = 0ull; accim[i][j] = 0ull; }

    const float* xrow = x + (size_t)b * NN * CC;
    const float* trow = t + (size_t)b * NN;

    for (int chunk = 0; chunk < NCHUNK; ++chunk) {
        const int n0 = g * NPB + chunk * TN;

        __syncthreads();   // previous MAC done: safe to overwrite tiles
        if (tid < TN) cols_sm[tid] = trow[n0 + tid] * 4095.0f;
        {
            const float4* xg  = (const float4*)(xrow + (size_t)n0 * CC);
            float4*       xs4 = (float4*)xs;
#pragma unroll
            for (int r = 0; r < 4; ++r) xs4[tid + 64 * r] = xg[tid + 64 * r];
        }
        __syncthreads();   // cols_sm / xs visible

        // ---- GEN: 32 (cos,sin) entries for row s_loc, 2 per iteration ----
        const ull* cols2 = (const ull*)cols_sm;
#pragma unroll 4
        for (int j = 0; j < TN / 2; ++j) {
            ull c2  = cols2[j];                        // {col_2j, col_2j+1}
            ull ph2 = mul2(r_s2, c2);                  // matches reference fp32 mul
            ull m2  = fma2n(ph2, inv2pi2, magic2);     // round-to-nearest int
            ull kf2 = add2(m2, nmagic2);
            ull rr2 = fma2n(kf2, nA2, ph2);            // Cody-Waite, exact prod
            rr2     = fma2n(kf2, nB2, rr2);            // rr in [-pi, pi]
            float2 rr = upk2(rr2);
            float sv0 = __sinf(rr.x), cv0 = __cosf(rr.x);
            float sv1 = __sinf(rr.y), cv1 = __cosf(rr.y);
            int col0 = (4 * j) ^ swz;
            int col1 = (4 * j + 2) ^ swz;
            *(float2*)(genrow + col0) = make_float2(cv0, sv0);
            *(float2*)(genrow + col1) = make_float2(cv1, sv1);
        }
        __syncthreads();   // cs_tile ready

        // ---- MAC: 4s x 8c, packed f32x2 FMAs ----
#pragma unroll 4
        for (int n = 0; n < TN; ++n) {
            const int c0 = (2 * n) ^ k2;
            const int c1 = c0 ^ 16;
            float2 cs0 = *(const float2*)(r0  + c0);
            float2 cs1 = *(const float2*)(r1  + c1);
            float2 cs2 = *(const float2*)(r2p + c0);
            float2 cs3 = *(const float2*)(r3  + c1);
            // x pairs loaded directly into 64-bit lanes: no packing MOVs
            const ulonglong2* xv = (const ulonglong2*)(xp + n * CC);
            ulonglong2 xa = xv[0];
            ulonglong2 xb = xv[1];
            ull xq[4] = { xa.x, xa.y, xb.x, xb.y };

            ull cc0 = pk2(cs0.x, cs0.x), ss0 = pk2(cs0.y, cs0.y);
            ull cc1 = pk2(cs1.x, cs1.x), ss1 = pk2(cs1.y, cs1.y);
            ull cc2 = pk2(cs2.x, cs2.x), ss2 = pk2(cs2.y, cs2.y);
            ull cc3 = pk2(cs3.x, cs3.x), ss3 = pk2(cs3.y, cs3.y);

#pragma unroll
            for (int j = 0; j < 4; ++j) {
                fma2(accre[0][j], cc0, xq[j]); fma2(accim[0][j], ss0, xq[j]);
                fma2(accre[1][j], cc1, xq[j]); fma2(accim[1][j], ss1, xq[j]);
                fma2(accre[2][j], cc2, xq[j]); fma2(accim[2][j], ss2, xq[j]);
                fma2(accre[3][j], cc3, xq[j]); fma2(accim[3][j], ss3, xq[j]);
            }
        }
    }

    // ---- write partials: scratch[(g*BB+b)][s][c] ----
    float2* scr = g_scratch + ((size_t)(g * BB + b) * SS + (size_t)stile * TS) * CC;
#pragma unroll
    for (int ii = 0; ii < 4; ++ii) {
        const int srow = sg * 4 + ii;
#pragma unroll
        for (int j = 0; j < 4; ++j) {
            float2 re2 = upk2(accre[ii][j]);
            float2 im2 = upk2(accim[ii][j]);
            const int c = cg * 8 + j * 2;
            scr[srow * CC + c]     = make_float2(re2.x, im2.x);
            scr[srow * CC + c + 1] = make_float2(re2.y, im2.y);
        }
    }
}

__global__ __launch_bounds__(256)
void fudft_reduce(float* __restrict__ out) {
    const int idx = blockIdx.x * blockDim.x + threadIdx.x;   // 0..524287
    float re = 0.0f, im = 0.0f;
#pragma unroll
    for (int g = 0; g < NSPLIT; ++g) {
        float2 p = g_scratch[(size_t)g * (BB * SS * CC) + idx];
        re += p.x; im += p.y;
    }
    float mag = sqrtf(fmaf(re, re, im * im)) * 0.015625f;    // * 1/sqrt(4096)
    const int s = (idx >> 5) & (SS - 1);
    if (s == 0 || s == SS - 1) mag = 0.0f;
    out[idx] = mag;
}

extern "C" void kernel_launch(void* const* d_in, const int* in_sizes, int n_in,
                              void* d_out, int out_size) {
    const float* x     = (const float*)d_in[0];   // [4,4096,32]
    const float* t     = (const float*)d_in[1];   // [4,4096]
    const float* freqs = (const float*)d_in[2];   // [4096]
    float* out = (float*)d_out;                   // [4,4096,32]

    fudft_partial<<<BB * (SS / TS) * NSPLIT, 64>>>(x, t, freqs);
    fudft_reduce<<<(BB * SS * CC) / 256, 256>>>(out);
}

// round 4
// speedup vs baseline: 3.8703x; 3.1578x over previous
#include <cuda_runtime.h>
#include <cstdint>
#include <math.h>

// Problem constants
#define BB 4
#define SS 4096
#define NN 4096
#define CC 32

#define KCH 64               // k (n) per staged chunk
#define NSTAGE (NN / KCH)    // 64
#define STILES (SS / 128)    // 32 s-tiles of 128 rows
#define NTHREADS 256         // 8 warps, each owns 16 s-rows
#define XPAD 40              // xs row stride in floats (bank = 8k+c, conflict-free)

typedef unsigned long long ull;

// ---- packed f32x2 helpers ----
__device__ __forceinline__ ull pk2(float lo, float hi) {
    ull r; asm("mov.b64 %0, {%1, %2};" : "=l"(r) : "f"(lo), "f"(hi)); return r;
}
__device__ __forceinline__ float2 upk2(ull v) {
    float lo, hi; asm("mov.b64 {%0, %1}, %2;" : "=f"(lo), "=f"(hi) : "l"(v));
    return make_float2(lo, hi);
}
__device__ __forceinline__ ull fma2n(ull a, ull b, ull c) {
    ull r; asm("fma.rn.f32x2 %0, %1, %2, %3;" : "=l"(r) : "l"(a), "l"(b), "l"(c)); return r;
}
__device__ __forceinline__ ull mul2(ull a, ull b) {
    ull r; asm("mul.rn.f32x2 %0, %1, %2;" : "=l"(r) : "l"(a), "l"(b)); return r;
}
__device__ __forceinline__ ull add2(ull a, ull b) {
    ull r; asm("add.rn.f32x2 %0, %1, %2;" : "=l"(r) : "l"(a), "l"(b)); return r;
}

// fp32 -> tf32 (round to nearest) as a raw b32 for mma operands
__device__ __forceinline__ uint32_t cvt_tf32(float v) {
    uint32_t r; asm("cvt.rna.tf32.f32 %0, %1;" : "=r"(r) : "f"(v)); return r;
}
__device__ __forceinline__ float cvt_tf32f(float v) {
    return __uint_as_float(cvt_tf32(v));
}

// m16n8k8 tf32 HMMA, D += A*B
__device__ __forceinline__ void mma8(float d[4], const uint32_t a[4],
                                     uint32_t b0, uint32_t b1) {
    asm volatile(
        "mma.sync.aligned.m16n8k8.row.col.f32.tf32.tf32.f32 "
        "{%0,%1,%2,%3}, {%4,%5,%6,%7}, {%8,%9}, {%0,%1,%2,%3};"
        : "+f"(d[0]), "+f"(d[1]), "+f"(d[2]), "+f"(d[3])
        : "r"(a[0]), "r"(a[1]), "r"(a[2]), "r"(a[3]), "r"(b0), "r"(b1));
}

// Range reduction: phase = k*2pi + r, |r| <= pi
#define INV2PI   0.15915493667125701904f
#define TWOPI_A  6.28318548202514648438f
#define TWOPI_B  (-1.74845552749343265e-7f)
#define MAGIC    12582912.0f    /* 1.5 * 2^23 */
#define ROWK     (-1.5339807878856412e-3f)   /* fl(-2*pi/4096) */

__global__ __launch_bounds__(NTHREADS, 1)
void fudft_hmma(const float* __restrict__ x,
                const float* __restrict__ t,
                const float* __restrict__ freqs,
                float* __restrict__ out) {
    __shared__ __align__(16) float cols_sm[NN];        // t*4095, whole batch-row
    __shared__ __align__(16) float xs[KCH * XPAD];     // X^T chunk, tf32-rounded

    const int tid  = threadIdx.x;
    const int wid  = tid >> 5;
    const int lane = tid & 31;
    const int g    = lane >> 2;     // group id 0..7
    const int qid  = lane & 3;      // thread-in-group

    const int bx    = blockIdx.x;   // 0..127
    const int stile = bx & (STILES - 1);
    const int b     = bx >> 5;

    // ---- stage cols for the whole batch row (once) ----
    {
        const float4* t4 = (const float4*)(t + (size_t)b * NN);
        float4* c4 = (float4*)cols_sm;
#pragma unroll
        for (int r = 0; r < NN / 4 / NTHREADS; ++r) {
            float4 v = t4[tid + NTHREADS * r];
            v.x *= 4095.0f; v.y *= 4095.0f; v.z *= 4095.0f; v.w *= 4095.0f;
            c4[tid + NTHREADS * r] = v;
        }
    }

    // ---- per-thread row frequencies (A-fragment rows g and g+8) ----
    const int s_base = stile * 128 + wid * 16;
    const float rs0 = (freqs[s_base + g]     * 4095.0f) * ROWK;
    const float rs1 = (freqs[s_base + g + 8] * 4095.0f) * ROWK;
    const ull rs0_2 = pk2(rs0, rs0);
    const ull rs1_2 = pk2(rs1, rs1);
    const ull inv2pi2 = pk2(INV2PI, INV2PI);
    const ull magic2  = pk2(MAGIC, MAGIC);
    const ull nmagic2 = pk2(-MAGIC, -MAGIC);
    const ull nA2     = pk2(-TWOPI_A, -TWOPI_A);
    const ull nB2     = pk2(-TWOPI_B, -TWOPI_B);

    float dre[4][4], dim[4][4];
#pragma unroll
    for (int nt = 0; nt < 4; ++nt)
#pragma unroll
        for (int j = 0; j < 4; ++j) { dre[nt][j] = 0.0f; dim[nt][j] = 0.0f; }

    const float4* xg = (const float4*)(x + (size_t)b * NN * CC);
    const int kk = tid >> 3;             // staging row (k) for fidx0
    const int cc = (tid & 7) * 4;        // staging col (c)

    // prefetch chunk 0 into registers
    float4 v0 = xg[tid];
    float4 v1 = xg[tid + NTHREADS];

#pragma unroll 1
    for (int st = 0; st < NSTAGE; ++st) {
        // store prefetched chunk (tf32-rounded)
        {
            float4 w0 = make_float4(cvt_tf32f(v0.x), cvt_tf32f(v0.y),
                                    cvt_tf32f(v0.z), cvt_tf32f(v0.w));
            float4 w1 = make_float4(cvt_tf32f(v1.x), cvt_tf32f(v1.y),
                                    cvt_tf32f(v1.z), cvt_tf32f(v1.w));
            *(float4*)(xs + kk * XPAD + cc)        = w0;
            *(float4*)(xs + (kk + 32) * XPAD + cc) = w1;
        }
        __syncthreads();

        // prefetch next chunk early (latency hidden behind compute)
        if (st < NSTAGE - 1) {
            v0 = xg[(st + 1) * 512 + tid];
            v1 = xg[(st + 1) * 512 + tid + NTHREADS];
        }

        const float* cols_loc = cols_sm + st * KCH;
        const float* bp  = xs + qid * XPAD + g;      // b0 base (k = qid)
        const float* bp4 = bp + 4 * XPAD;            // b1 base (k = qid+4)

#pragma unroll
        for (int ks = 0; ks < 8; ++ks) {
            const int k0 = ks * 8;
            // phases for the 4 A-fragment slots
            const float colA = cols_loc[k0 + qid];
            const float colB = cols_loc[k0 + qid + 4];
            const ull tAB = pk2(colA, colB);
            ull ph0 = mul2(rs0_2, tAB);
            ull ph1 = mul2(rs1_2, tAB);
            ull m0 = fma2n(ph0, inv2pi2, magic2);
            ull m1 = fma2n(ph1, inv2pi2, magic2);
            ull k0v = add2(m0, nmagic2);
            ull k1v = add2(m1, nmagic2);
            ull r0v = fma2n(k0v, nA2, ph0); r0v = fma2n(k0v, nB2, r0v);
            ull r1v = fma2n(k1v, nA2, ph1); r1v = fma2n(k1v, nB2, r1v);
            const float2 ra = upk2(r0v);   // (rs0*colA, rs0*colB)
            const float2 rb = upk2(r1v);   // (rs1*colA, rs1*colB)

            uint32_t ac[4], as_[4];
            ac[0] = cvt_tf32(__cosf(ra.x)); as_[0] = cvt_tf32(__sinf(ra.x));
            ac[1] = cvt_tf32(__cosf(rb.x)); as_[1] = cvt_tf32(__sinf(rb.x));
            ac[2] = cvt_tf32(__cosf(ra.y)); as_[2] = cvt_tf32(__sinf(ra.y));
            ac[3] = cvt_tf32(__cosf(rb.y)); as_[3] = cvt_tf32(__sinf(rb.y));

            // B fragments + MMAs, 4 n-tiles
            const float* b0p = bp  + k0 * XPAD;
            const float* b1p = bp4 + k0 * XPAD;
#pragma unroll
            for (int nt = 0; nt < 4; ++nt) {
                const uint32_t b0 = __float_as_uint(b0p[nt * 8]);
                const uint32_t b1 = __float_as_uint(b1p[nt * 8]);
                mma8(dre[nt], ac,  b0, b1);
                mma8(dim[nt], as_, b0, b1);
            }
        }
        __syncthreads();
    }

    // ---- epilogue: magnitudes straight from register accumulators ----
    const int s0 = s_base + g;
    const int s1 = s0 + 8;
    const bool z0 = (s0 == 0) || (s0 == SS - 1);
    const bool z1 = (s1 == 0) || (s1 == SS - 1);
    float* o0 = out + ((size_t)b * SS + s0) * CC;
    float* o1 = out + ((size_t)b * SS + s1) * CC;
#pragma unroll
    for (int nt = 0; nt < 4; ++nt) {
        const int c = nt * 8 + 2 * qid;
        float2 w;
        w.x = z0 ? 0.0f : sqrtf(fmaf(dre[nt][0], dre[nt][0], dim[nt][0] * dim[nt][0])) * 0.015625f;
        w.y = z0 ? 0.0f : sqrtf(fmaf(dre[nt][1], dre[nt][1], dim[nt][1] * dim[nt][1])) * 0.015625f;
        *(float2*)(o0 + c) = w;
        w.x = z1 ? 0.0f : sqrtf(fmaf(dre[nt][2], dre[nt][2], dim[nt][2] * dim[nt][2])) * 0.015625f;
        w.y = z1 ? 0.0f : sqrtf(fmaf(dre[nt][3], dre[nt][3], dim[nt][3] * dim[nt][3])) * 0.015625f;
        *(float2*)(o1 + c) = w;
    }
}

extern "C" void kernel_launch(void* const* d_in, const int* in_sizes, int n_in,
                              void* d_out, int out_size) {
    const float* x     = (const float*)d_in[0];   // [4,4096,32]
    const float* t     = (const float*)d_in[1];   // [4,4096]
    const float* freqs = (const float*)d_in[2];   // [4096]
    float* out = (float*)d_out;                   // [4,4096,32]

    fudft_hmma<<<BB * STILES, NTHREADS>>>(x, t, freqs, out);
}